// round 12
// baseline (speedup 1.0000x reference)
#include <cuda_runtime.h>
#include <cuda_fp16.h>
#include <cstdint>
#include <math.h>

#define NB   4
#define NPT  4096
#define NS   4096
#define CIND 128
#define DIMD 64
#define KNNK 20
#define MTOT (NB*NPT*KNNK)   /* 327680 */
#define PTOT (NB*NPT)        /* 16384  */
#define MT   80              /* 4 whole points per CTA */

// ---------------- static device scratch (no runtime allocation) ----------------
__device__ float g_q[PTOT*DIMD];
__device__ float g_k[PTOT*DIMD];
__device__ float g_v[PTOT*DIMD];
__device__ int   g_idx[PTOT*KNNK];
__device__ __half g_hh[MTOT*DIMD];    // h (fp16, single plane)
__device__ float g_vg[MTOT*DIMD];     // [m][d]
__device__ float g_agg[PTOT*2*DIMD];  // [q][d], q = point*2+r
__device__ float g_wet[64*128];       // [d][o2]  transposed we
__device__ float g_abn[512];          // [0:256) inv, [256:512) fused bias
// fragment-ordered, fp16 hi/lo-split weights: uint4 = (b0hi, b1hi, b0lo, b1lo)
__device__ unsigned g_w1f[4*32*32*4];   // [s<4][nfg<32][lane][4]
__device__ unsigned g_w2f[16*16*32*4];  // [s<16][nfg<16][lane][4]

// ---------------- helpers ----------------
__device__ __forceinline__ void mma_f16(float* d, const unsigned* a, const unsigned* b) {
    asm volatile(
        "mma.sync.aligned.m16n8k16.row.col.f32.f16.f16.f32 "
        "{%0,%1,%2,%3}, {%4,%5,%6,%7}, {%8,%9}, {%0,%1,%2,%3};"
        : "+f"(d[0]), "+f"(d[1]), "+f"(d[2]), "+f"(d[3])
        : "r"(a[0]), "r"(a[1]), "r"(a[2]), "r"(a[3]), "r"(b[0]), "r"(b[1]));
}
__device__ __forceinline__ void ldsm_x4(unsigned* r, uint32_t addr) {
    asm volatile("ldmatrix.sync.aligned.m8n8.x4.shared.b16 {%0,%1,%2,%3}, [%4];"
        : "=r"(r[0]), "=r"(r[1]), "=r"(r[2]), "=r"(r[3]) : "r"(addr));
}
__device__ __forceinline__ uint32_t smem_u32(const void* p) {
    uint32_t a;
    asm("{ .reg .u64 t; cvta.to.shared.u64 t, %1; cvt.u32.u64 %0, t; }" : "=r"(a) : "l"(p));
    return a;
}
// fp16 exact-pair split for weights: b = hi + lo with lo = fp16(b - hi)
__device__ __forceinline__ void split_f16(float x, __half* hi, __half* lo) {
    __half h = __float2half(x);
    *hi = h;
    *lo = __float2half(x - __half2float(h));
}

// ============================================================================
// Setup: fp16 hi/lo split + fragment-order the GEMM weights; fold BN; we^T.
// ============================================================================
__global__ void setup_kernel(const float* __restrict__ aw1, const float* __restrict__ awt,
                             const float* __restrict__ we,  const float* __restrict__ ag,
                             const float* __restrict__ av,  const float* __restrict__ ab1,
                             const float* __restrict__ am,  const float* __restrict__ abt2)
{
    int i0 = blockIdx.x*256 + threadIdx.x;
    int stride = gridDim.x*256;

    for (int i=i0; i<4*32*32; i+=stride) {
        int lane = i & 31, nfg = (i>>5)&31, s = i>>10;
        int gr = lane>>2, tig = lane&3;
        int n = nfg*8 + gr;
        int k0 = s*16 + 2*tig;
        float bk[4] = { aw1[n*64 + k0],     aw1[n*64 + k0+1],
                        aw1[n*64 + k0+8],   aw1[n*64 + k0+9] };
        __half hi[4], lo[4];
        #pragma unroll
        for (int j=0;j<4;++j) split_f16(bk[j], &hi[j], &lo[j]);
        unsigned* dst = &g_w1f[i*4];
        __half2 p;
        p = __halves2half2(hi[0], hi[1]); dst[0] = *(unsigned*)&p;
        p = __halves2half2(hi[2], hi[3]); dst[1] = *(unsigned*)&p;
        p = __halves2half2(lo[0], lo[1]); dst[2] = *(unsigned*)&p;
        p = __halves2half2(lo[2], lo[3]); dst[3] = *(unsigned*)&p;
    }
    for (int i=i0; i<16*16*32; i+=stride) {
        int lane = i & 31, nfg = (i>>5)&15, s = i>>9;
        int gr = lane>>2, tig = lane&3;
        int n = nfg*8 + gr;
        int k0 = s*16 + 2*tig;
        int nn = (n&63)*2 + (n>>6);
        float bk[4] = { awt[(k0  )*128 + nn], awt[(k0+1)*128 + nn],
                        awt[(k0+8)*128 + nn], awt[(k0+9)*128 + nn] };
        __half hi[4], lo[4];
        #pragma unroll
        for (int j=0;j<4;++j) split_f16(bk[j], &hi[j], &lo[j]);
        unsigned* dst = &g_w2f[i*4];
        __half2 p;
        p = __halves2half2(hi[0], hi[1]); dst[0] = *(unsigned*)&p;
        p = __halves2half2(hi[2], hi[3]); dst[1] = *(unsigned*)&p;
        p = __halves2half2(lo[0], lo[1]); dst[2] = *(unsigned*)&p;
        p = __halves2half2(lo[2], lo[3]); dst[3] = *(unsigned*)&p;
    }
    for (int i=i0; i<64*128; i+=stride) { int d=i>>7, o2=i&127; g_wet[i] = we[o2*64+d]; }
    for (int i=i0; i<256; i+=stride) {
        float inv = ag[i]*rsqrtf(av[i]+1e-5f);
        g_abn[i]     = inv;
        g_abn[256+i] = (ab1[i]-am[i])*inv + abt2[i];
    }
}

// ============================================================================
// Kernel 1: q/k/v 1x1 conv.
// ============================================================================
__global__ __launch_bounds__(256) void qkv_kernel(
    const float* __restrict__ query, const float* __restrict__ key_feat,
    const float* __restrict__ wq, const float* __restrict__ bq,
    const float* __restrict__ wk, const float* __restrict__ bk,
    const float* __restrict__ wv, const float* __restrict__ bv)
{
    __shared__ float Wsm[64*129];
    __shared__ __align__(16) float xs[128*16];
    int t = threadIdx.x;
    int z = blockIdx.z;
    const float* W    = (z==0)? wq : (z==1)? wk : wv;
    const float* bias = (z==0)? bq : (z==1)? bk : bv;
    const float* inp  = (z==0)? query : key_feat;
    float* outp       = (z==0)? g_q : (z==1)? g_k : g_v;
    int b  = blockIdx.y;
    int n0 = blockIdx.x * 16;

    for (int idx=t; idx<64*128; idx+=256) Wsm[(idx>>7)*129 + (idx&127)] = W[idx];
    for (int idx=t; idx<128*16; idx+=256) {
        int c = idx>>4, i = idx&15;
        xs[c*16+i] = inp[(b*CIND+c)*NPT + n0 + i];
    }
    __syncthreads();

    int d = t & 63, g = t >> 6;
    float bb = bias[d];
    float acc0=bb, acc1=bb, acc2=bb, acc3=bb;
    for (int c=0; c<128; ++c) {
        float w = Wsm[d*129+c];
        float4 v4 = *(const float4*)&xs[c*16 + g*4];
        acc0 += w*v4.x; acc1 += w*v4.y; acc2 += w*v4.z; acc3 += w*v4.w;
    }
    int pb = (b*NPT + n0 + g*4);
    outp[(pb+0)*DIMD + d] = acc0;
    outp[(pb+1)*DIMD + d] = acc1;
    outp[(pb+2)*DIMD + d] = acc2;
    outp[(pb+3)*DIMD + d] = acc3;
}

// ============================================================================
// Kernel 2: KNN (top-20 smallest d = |p1|^2+|p2|^2-2 p1.p2, stable ties).
// ============================================================================
__global__ __launch_bounds__(128) void knn_kernel(
    const float* __restrict__ pos1, const float* __restrict__ pos2)
{
    __shared__ float4 sp[2048];
    int t = threadIdx.x;
    int b = blockIdx.y;
    int n = blockIdx.x*128 + t;
    const float* p1 = pos1 + b*3*NPT;
    float qx = p1[n], qy = p1[NPT+n], qz = p1[2*NPT+n];
    float s1 = qx*qx + qy*qy + qz*qz;

    float bd[KNNK]; int bi[KNNK];
    #pragma unroll
    for (int i=0;i<KNNK;++i) { bd[i]=1e30f; bi[i]=0; }

    const float* p2 = pos2 + b*3*NS;
    for (int ch=0; ch<2; ++ch) {
        __syncthreads();
        for (int j=t; j<2048; j+=128) {
            int jg = ch*2048 + j;
            float x=p2[jg], y=p2[NS+jg], z=p2[2*NS+jg];
            sp[j] = make_float4(x, y, z, x*x+y*y+z*z);
        }
        __syncthreads();
        for (int j=0; j<2048; ++j) {
            float4 p = sp[j];
            float dd = s1 + p.w - 2.0f*(qx*p.x + qy*p.y + qz*p.z);
            if (dd < bd[KNNK-1]) {
                int jg = ch*2048 + j;
                #pragma unroll
                for (int i=KNNK-1; i>=1; --i) {
                    if (dd < bd[i]) {
                        bool sh = dd < bd[i-1];
                        bd[i] = sh ? bd[i-1] : dd;
                        bi[i] = sh ? bi[i-1] : jg;
                    }
                }
                if (dd < bd[0]) { bd[0]=dd; bi[0]=jg; }
            }
        }
    }
    int* op = &g_idx[(b*NPT + n)*KNNK];
    #pragma unroll
    for (int i=0;i<KNNK;++i) op[i] = bi[i];
}

// ============================================================================
// Kernel 3: gather + pos-MLP; h = q - k_g + pe (fp16 plane); vg fp32.
// ============================================================================
__global__ __launch_bounds__(128) void prep_kernel(
    const float* __restrict__ pos1, const float* __restrict__ pos2,
    const float* __restrict__ pw1, const float* __restrict__ pb1,
    const float* __restrict__ pg,  const float* __restrict__ pbt,
    const float* __restrict__ pm,  const float* __restrict__ pvv,
    const float* __restrict__ pw2, const float* __restrict__ pb2)
{
    __shared__ float pw2s[64*65];
    __shared__ __align__(16) float pe1s[2][64*24];
    __shared__ float prel[2][3][KNNK];
    __shared__ float qs[2][64];
    __shared__ int idxs[2][KNNK];
    int t = threadIdx.x;
    int p0 = blockIdx.x*2;

    for (int idx=t; idx<64*64; idx+=128) pw2s[(idx>>6)*65 + (idx&63)] = pw2[idx];
    if (t < 2*KNNK) idxs[t/KNNK][t%KNNK] = g_idx[p0*KNNK + t];
    {
        int pp = t>>6, d = t&63;
        qs[pp][d] = g_q[(p0+pp)*DIMD + d];
    }
    __syncthreads();

    if (t < 2*3*KNNK) {
        int pp = t/(3*KNNK), r = t%(3*KNNK);
        int c = r/KNNK, k = r%KNNK;
        int p = p0+pp, b = p>>12, n = p&4095;
        prel[pp][c][k] = pos1[(b*3+c)*NPT + n] - pos2[(b*3+c)*NS + idxs[pp][k]];
    }
    __syncthreads();

    {
        int cH = t & 63, pp = t >> 6;
        float w0 = pw1[cH*3], w1 = pw1[cH*3+1], w2v = pw1[cH*3+2];
        float inv = pg[cH]*rsqrtf(pvv[cH]+1e-5f);
        float tb  = (pb1[cH]-pm[cH])*inv + pbt[cH];
        #pragma unroll
        for (int k=0;k<KNNK;++k) {
            float s = w0*prel[pp][0][k] + w1*prel[pp][1][k] + w2v*prel[pp][2][k];
            pe1s[pp][cH*24+k] = fmaxf(s*inv + tb, 0.0f);
        }
    }
    __syncthreads();

    {
        int d = t&63, pp = t>>6;
        int p = p0+pp, b = p>>12;
        float acc[KNNK]; float bias = pb2[d];
        #pragma unroll
        for (int k=0;k<KNNK;++k) acc[k]=bias;
        for (int cH=0;cH<64;++cH) {
            float w = pw2s[d*65+cH];
            #pragma unroll
            for (int k4=0;k4<5;++k4) {
                float4 v4 = *(const float4*)&pe1s[pp][cH*24 + k4*4];
                acc[k4*4+0]+=w*v4.x; acc[k4*4+1]+=w*v4.y;
                acc[k4*4+2]+=w*v4.z; acc[k4*4+3]+=w*v4.w;
            }
        }
        float qv = qs[pp][d];
        #pragma unroll
        for (int k=0;k<KNNK;++k) {
            int j = idxs[pp][k];
            int m = p*KNNK + k;
            float kg = g_k[(b*NS+j)*DIMD + d];
            float vv = g_v[(b*NS+j)*DIMD + d];
            float hv = qv - kg + acc[k];
            g_hh[m*DIMD + d] = __float2half(hv);
            g_vg[m*DIMD + d] = vv + acc[k];
        }
    }
}

// ============================================================================
// Kernel 4 (FULLY FUSED): gemm1 + BN/ReLU + gemm2 + softmax + aggregation.
// CTA = 80 m-rows (4 whole points), block 320 = 10 warps (mw = w>>1 in 0..4,
// cw = w&1). 2-product fp16 mma.m16n8k16 + ldmatrix, as R9.
// smem: hst [80m][64k] fp16 (stride 36 words) 11.5KB
//       ast [80m][256k] fp16 (stride 132 words) 42.2KB — ALIASED by logits
//       ls  [80m][128o'] fp32 (stride 132) — same region as ast (dead after
//            phase-2 mainloop; __syncthreads separates)
//       vgs [80m][64d] fp32 20.5KB
// total 74240 B -> 2 CTAs/SM.
// ============================================================================
#define HSTW 36
#define ASTW 132
#define OFF_HST 0
#define OFF_AST (MT*HSTW)
#define OFF_VG  (MT*HSTW + MT*ASTW)
#define SMEM_ATTN ((MT*HSTW + MT*ASTW + MT*64)*4)

__global__ __launch_bounds__(320, 2) void attn_gemm_kernel()
{
    extern __shared__ __align__(16) unsigned smu[];
    unsigned* hst = smu + OFF_HST;
    unsigned* ast = smu + OFF_AST;
    float*    ls  = (float*)(smu + OFF_AST);   // alias (phase ordering via barriers)
    float*    vgs = (float*)(smu + OFF_VG);
    int t = threadIdx.x;
    int w = t >> 5, lane = t & 31;
    int gr = lane >> 2, tig = lane & 3;
    int mw = w >> 1, cw = w & 1;
    int m0 = blockIdx.x * MT;

    // ldmatrix lane geometry
    int lr  = lane & 7;
    int lm8 = (lane >> 3) & 1;
    int lk8 = (lane >> 4) & 1;

    // stage h plane (32 words of 2 fp16 per row)
    {
        const unsigned* hw = (const unsigned*)g_hh;
        for (int idx = t; idx < MT*32; idx += 320) {
            int m = idx >> 5, wk = idx & 31;
            hst[m*HSTW + wk] = hw[(m0+m)*32 + wk];
        }
    }
    __syncthreads();

    uint32_t hb = smem_u32(hst);
    uint32_t ab = smem_u32(ast);
    int row = mw*16 + lm8*8 + lr;

    // ---------------- phase 1: 80m x 256c, K=64 (4 k16 steps) ----------------
    {
        float acc[16][4];
        #pragma unroll
        for (int nf=0;nf<16;++nf)
            #pragma unroll
            for (int q=0;q<4;++q) acc[nf][q] = 0.f;

        uint32_t ad = hb + (uint32_t)row*(HSTW*4) + (uint32_t)lk8*16;

        #pragma unroll
        for (int s=0; s<4; ++s) {
            unsigned av[4];
            ldsm_x4(av, ad + s*32);
            #pragma unroll
            for (int q4=0; q4<4; ++q4) {
                uint4 wf[4];
                #pragma unroll
                for (int j=0;j<4;++j) {
                    int nfg = cw*16 + q4*4 + j;
                    wf[j] = __ldg((const uint4*)&g_w1f[((s*32 + nfg)*32 + lane)*4]);
                }
                #pragma unroll
                for (int j=0;j<4;++j) {
                    int nf = q4*4 + j;
                    unsigned bhi[2] = {wf[j].x, wf[j].y};
                    unsigned blo[2] = {wf[j].z, wf[j].w};
                    mma_f16(acc[nf], av, bhi);
                    mma_f16(acc[nf], av, blo);
                }
            }
        }

        // epilogue: BN + ReLU -> fp16 ast plane
        #pragma unroll
        for (int nf=0;nf<16;++nf) {
            int cb = cw*128 + nf*8 + 2*tig;
            int wd = cw*64 + nf*4 + tig;
            float2 iv = __ldg((const float2*)&g_abn[cb]);
            float2 tb = __ldg((const float2*)&g_abn[256+cb]);
            int r0 = mw*16 + gr;
            float v0 = fmaxf(fmaf(acc[nf][0], iv.x, tb.x), 0.f);
            float v1 = fmaxf(fmaf(acc[nf][1], iv.y, tb.y), 0.f);
            float v2 = fmaxf(fmaf(acc[nf][2], iv.x, tb.x), 0.f);
            float v3 = fmaxf(fmaf(acc[nf][3], iv.y, tb.y), 0.f);
            __half2 p0 = __halves2half2(__float2half(v0), __float2half(v1));
            __half2 p1 = __halves2half2(__float2half(v2), __float2half(v3));
            ast[(r0  )*ASTW + wd] = *(unsigned*)&p0;
            ast[(r0+8)*ASTW + wd] = *(unsigned*)&p1;
        }
    }
    // stage vg tile while here (needed only after phase 2)
    for (int idx = t; idx < MT*64; idx += 320)
        vgs[idx] = g_vg[(size_t)m0*64 + idx];
    __syncthreads();

    // ---------------- phase 2: 80m x 128o', K=256 (16 k16 steps) ----------------
    float acc2[8][4];
    {
        #pragma unroll
        for (int nf=0;nf<8;++nf)
            #pragma unroll
            for (int q=0;q<4;++q) acc2[nf][q] = 0.f;

        uint32_t ad = ab + (uint32_t)row*(ASTW*4) + (uint32_t)lk8*16;

        #pragma unroll 4
        for (int s=0; s<16; ++s) {
            unsigned av[4];
            ldsm_x4(av, ad + s*32);
            uint4 wf[4];
            #pragma unroll
            for (int j=0;j<4;++j) {
                int nfg = cw*8 + j;
                wf[j] = __ldg((const uint4*)&g_w2f[((s*16 + nfg)*32 + lane)*4]);
            }
            uint4 wf2[4];
            #pragma unroll
            for (int j=0;j<4;++j) {
                int nfg = cw*8 + 4 + j;
                wf2[j] = __ldg((const uint4*)&g_w2f[((s*16 + nfg)*32 + lane)*4]);
            }
            #pragma unroll
            for (int j=0;j<4;++j) {
                unsigned bhi[2] = {wf[j].x, wf[j].y};
                unsigned blo[2] = {wf[j].z, wf[j].w};
                mma_f16(acc2[j], av, bhi);
                mma_f16(acc2[j], av, blo);
            }
            #pragma unroll
            for (int j=0;j<4;++j) {
                unsigned bhi[2] = {wf2[j].x, wf2[j].y};
                unsigned blo[2] = {wf2[j].z, wf2[j].w};
                mma_f16(acc2[4+j], av, bhi);
                mma_f16(acc2[4+j], av, blo);
            }
        }
    }
    __syncthreads();   // all ast reads complete before logits overwrite

    // ---- epilogue 2: logits -> smem (aliasing ast) ----
    #pragma unroll
    for (int nf=0;nf<8;++nf) {
        int ob = cw*64 + nf*8 + 2*tig;
        int r0 = mw*16 + gr;
        *(float2*)&ls[(r0  )*ASTW + ob] = make_float2(acc2[nf][0], acc2[nf][1]);
        *(float2*)&ls[(r0+8)*ASTW + ob] = make_float2(acc2[nf][2], acc2[nf][3]);
    }
    __syncthreads();

    // ---- softmax over k (=20) + aggregation ----
    for (int idx = t; idx < 4*128; idx += 320) {
        int pp = idx >> 7, chn = idx & 127;
        int d = chn & 63;
        const float* lp = &ls[(pp*KNNK)*ASTW + chn];
        float lg[KNNK];
        #pragma unroll
        for (int k=0;k<KNNK;++k) lg[k] = lp[k*ASTW];
        float mx = lg[0];
        #pragma unroll
        for (int k=1;k<KNNK;++k) mx = fmaxf(mx, lg[k]);
        float s = 0.f;
        #pragma unroll
        for (int k=0;k<KNNK;++k) { lg[k] = __expf(lg[k]-mx); s += lg[k]; }
        float inv = 1.f/s;
        const float* vp = &vgs[(pp*KNNK)*64 + d];
        float acc = 0.f;
        #pragma unroll
        for (int k=0;k<KNNK;++k) acc += lg[k]*vp[k*64];
        g_agg[(blockIdx.x*4 + pp)*128 + chn] = acc*inv;
    }
}

// ============================================================================
// Kernel 5: final 1x1 conv (DIM->CIN) + residual (nearest-upsampled query).
// ============================================================================
__global__ __launch_bounds__(256) void final_kernel(
    const float* __restrict__ query, const float* __restrict__ be,
    float* __restrict__ out)
{
    __shared__ float wes[64*128];
    __shared__ __align__(16) float aggt[64*16];
    int t = threadIdx.x;
    int q0 = blockIdx.x*16;
    for (int idx=t; idx<64*128; idx+=256) wes[idx] = g_wet[idx];
    for (int idx=t; idx<16*64; idx+=256) {
        int li = idx>>6, d = idx&63;
        aggt[d*16+li] = g_agg[(q0+li)*64 + d];
    }
    __syncthreads();

    int o2 = t & 127, h = t >> 7;
    float acc[8];
    #pragma unroll
    for (int i=0;i<8;++i) acc[i]=0.f;
    for (int d=0; d<64; ++d) {
        float w = wes[d*128+o2];
        float4 a0 = *(const float4*)&aggt[d*16 + h*8];
        float4 a1 = *(const float4*)&aggt[d*16 + h*8 + 4];
        acc[0]+=w*a0.x; acc[1]+=w*a0.y; acc[2]+=w*a0.z; acc[3]+=w*a0.w;
        acc[4]+=w*a1.x; acc[5]+=w*a1.y; acc[6]+=w*a1.z; acc[7]+=w*a1.w;
    }
    float bb = be[o2];
    #pragma unroll
    for (int i=0;i<8;++i) {
        int qq = q0 + h*8 + i;
        int b = qq >> 13, nr = qq & 8191, n = nr >> 1;
        out[b*(128*8192) + o2*8192 + nr] = acc[i] + bb
            + query[b*(128*4096) + o2*4096 + n];
    }
}

// ============================================================================
extern "C" void kernel_launch(void* const* d_in, const int* in_sizes, int n_in,
                              void* d_out, int out_size)
{
    const float* pos1     = (const float*)d_in[0];
    const float* query    = (const float*)d_in[1];
    const float* pos2     = (const float*)d_in[2];
    const float* key_feat = (const float*)d_in[3];
    const float* wq  = (const float*)d_in[4];
    const float* bq  = (const float*)d_in[5];
    const float* wk  = (const float*)d_in[6];
    const float* bk  = (const float*)d_in[7];
    const float* wv  = (const float*)d_in[8];
    const float* bv  = (const float*)d_in[9];
    const float* pw1 = (const float*)d_in[10];
    const float* pb1 = (const float*)d_in[11];
    const float* pg  = (const float*)d_in[12];
    const float* pbt = (const float*)d_in[13];
    const float* pm  = (const float*)d_in[14];
    const float* pv  = (const float*)d_in[15];
    const float* pw2 = (const float*)d_in[16];
    const float* pb2 = (const float*)d_in[17];
    const float* aw1 = (const float*)d_in[18];
    const float* ab1 = (const float*)d_in[19];
    const float* ag  = (const float*)d_in[20];
    const float* abt2= (const float*)d_in[21];
    const float* am  = (const float*)d_in[22];
    const float* av  = (const float*)d_in[23];
    const float* awt = (const float*)d_in[24];
    /* abt (d_in[25]) is constant along the softmax axis -> dropped */
    const float* we  = (const float*)d_in[26];
    const float* be  = (const float*)d_in[27];
    float* out = (float*)d_out;

    static int smem_set = 0;
    if (!smem_set) {
        cudaFuncSetAttribute(attn_gemm_kernel,
            cudaFuncAttributeMaxDynamicSharedMemorySize, SMEM_ATTN);
        smem_set = 1;
    }

    setup_kernel<<<96, 256>>>(aw1, awt, we, ag, av, ab1, am, abt2);
    qkv_kernel<<<dim3(256, NB, 3), 256>>>(query, key_feat, wq, bq, wk, bk, wv, bv);
    knn_kernel<<<dim3(32, NB), 128>>>(pos1, pos2);
    prep_kernel<<<PTOT/2, 128>>>(pos1, pos2, pw1, pb1, pg, pbt, pm, pv, pw2, pb2);
    attn_gemm_kernel<<<MTOT/MT, 320, SMEM_ATTN>>>();
    final_kernel<<<PTOT*2/16, 256>>>(query, be, out);
}

// round 13
// speedup vs baseline: 1.1832x; 1.1832x over previous
#include <cuda_runtime.h>
#include <cuda_fp16.h>
#include <cstdint>
#include <math.h>

#define NB   4
#define NPT  4096
#define NS   4096
#define CIND 128
#define DIMD 64
#define KNNK 20
#define MTOT (NB*NPT*KNNK)   /* 327680 */
#define PTOT (NB*NPT)        /* 16384  */

// ---------------- static device scratch (no runtime allocation) ----------------
__device__ float g_q[PTOT*DIMD];
__device__ float g_k[PTOT*DIMD];
__device__ float g_v[PTOT*DIMD];
__device__ int   g_idx[PTOT*KNNK];
__device__ __half g_hh[MTOT*DIMD];    // h (fp16, single plane)
__device__ float g_vg[MTOT*DIMD];     // [m][d]
__device__ float g_logits[MTOT*128];  // [m][r*64+o]
__device__ float g_agg[PTOT*2*DIMD];  // [q][d], q = point*2+r
__device__ float g_wet[64*128];       // [d][o2]  transposed we
__device__ float g_pw2t[64*64];       // [cH][d]  transposed pw2 (prep weight)
__device__ float g_abn[512];          // [0:256) inv, [256:512) fused bias
// fragment-ordered, fp16 hi/lo-split weights: uint4 = (b0hi, b1hi, b0lo, b1lo)
__device__ unsigned g_w1f[4*32*32*4];   // [s<4][nfg<32][lane][4]
__device__ unsigned g_w2f[16*16*32*4];  // [s<16][nfg<16][lane][4]

// ---------------- helpers ----------------
__device__ __forceinline__ void mma_f16(float* d, const unsigned* a, const unsigned* b) {
    asm volatile(
        "mma.sync.aligned.m16n8k16.row.col.f32.f16.f16.f32 "
        "{%0,%1,%2,%3}, {%4,%5,%6,%7}, {%8,%9}, {%0,%1,%2,%3};"
        : "+f"(d[0]), "+f"(d[1]), "+f"(d[2]), "+f"(d[3])
        : "r"(a[0]), "r"(a[1]), "r"(a[2]), "r"(a[3]), "r"(b[0]), "r"(b[1]));
}
__device__ __forceinline__ void ldsm_x4(unsigned* r, uint32_t addr) {
    asm volatile("ldmatrix.sync.aligned.m8n8.x4.shared.b16 {%0,%1,%2,%3}, [%4];"
        : "=r"(r[0]), "=r"(r[1]), "=r"(r[2]), "=r"(r[3]) : "r"(addr));
}
__device__ __forceinline__ uint32_t smem_u32(const void* p) {
    uint32_t a;
    asm("{ .reg .u64 t; cvta.to.shared.u64 t, %1; cvt.u32.u64 %0, t; }" : "=r"(a) : "l"(p));
    return a;
}
// fp16 exact-pair split for weights: b = hi + lo with lo = fp16(b - hi)
__device__ __forceinline__ void split_f16(float x, __half* hi, __half* lo) {
    __half h = __float2half(x);
    *hi = h;
    *lo = __float2half(x - __half2float(h));
}

// ============================================================================
// Setup: fp16 hi/lo split + fragment-order the GEMM weights; fold BN;
// transpose we and pw2.
// ============================================================================
__global__ void setup_kernel(const float* __restrict__ aw1, const float* __restrict__ awt,
                             const float* __restrict__ we,  const float* __restrict__ ag,
                             const float* __restrict__ av,  const float* __restrict__ ab1,
                             const float* __restrict__ am,  const float* __restrict__ abt2,
                             const float* __restrict__ pw2)
{
    int i0 = blockIdx.x*256 + threadIdx.x;
    int stride = gridDim.x*256;

    for (int i=i0; i<4*32*32; i+=stride) {
        int lane = i & 31, nfg = (i>>5)&31, s = i>>10;
        int gr = lane>>2, tig = lane&3;
        int n = nfg*8 + gr;
        int k0 = s*16 + 2*tig;
        float bk[4] = { aw1[n*64 + k0],     aw1[n*64 + k0+1],
                        aw1[n*64 + k0+8],   aw1[n*64 + k0+9] };
        __half hi[4], lo[4];
        #pragma unroll
        for (int j=0;j<4;++j) split_f16(bk[j], &hi[j], &lo[j]);
        unsigned* dst = &g_w1f[i*4];
        __half2 p;
        p = __halves2half2(hi[0], hi[1]); dst[0] = *(unsigned*)&p;
        p = __halves2half2(hi[2], hi[3]); dst[1] = *(unsigned*)&p;
        p = __halves2half2(lo[0], lo[1]); dst[2] = *(unsigned*)&p;
        p = __halves2half2(lo[2], lo[3]); dst[3] = *(unsigned*)&p;
    }
    for (int i=i0; i<16*16*32; i+=stride) {
        int lane = i & 31, nfg = (i>>5)&15, s = i>>9;
        int gr = lane>>2, tig = lane&3;
        int n = nfg*8 + gr;
        int k0 = s*16 + 2*tig;
        int nn = (n&63)*2 + (n>>6);
        float bk[4] = { awt[(k0  )*128 + nn], awt[(k0+1)*128 + nn],
                        awt[(k0+8)*128 + nn], awt[(k0+9)*128 + nn] };
        __half hi[4], lo[4];
        #pragma unroll
        for (int j=0;j<4;++j) split_f16(bk[j], &hi[j], &lo[j]);
        unsigned* dst = &g_w2f[i*4];
        __half2 p;
        p = __halves2half2(hi[0], hi[1]); dst[0] = *(unsigned*)&p;
        p = __halves2half2(hi[2], hi[3]); dst[1] = *(unsigned*)&p;
        p = __halves2half2(lo[0], lo[1]); dst[2] = *(unsigned*)&p;
        p = __halves2half2(lo[2], lo[3]); dst[3] = *(unsigned*)&p;
    }
    for (int i=i0; i<64*128; i+=stride) { int d=i>>7, o2=i&127; g_wet[i] = we[o2*64+d]; }
    for (int i=i0; i<64*64; i+=stride) { int cH=i>>6, d=i&63; g_pw2t[i] = pw2[d*64+cH]; }
    for (int i=i0; i<256; i+=stride) {
        float inv = ag[i]*rsqrtf(av[i]+1e-5f);
        g_abn[i]     = inv;
        g_abn[256+i] = (ab1[i]-am[i])*inv + abt2[i];
    }
}

// ============================================================================
// Kernel 1: q/k/v 1x1 conv.
// ============================================================================
__global__ __launch_bounds__(256) void qkv_kernel(
    const float* __restrict__ query, const float* __restrict__ key_feat,
    const float* __restrict__ wq, const float* __restrict__ bq,
    const float* __restrict__ wk, const float* __restrict__ bk,
    const float* __restrict__ wv, const float* __restrict__ bv)
{
    __shared__ float Wsm[64*129];
    __shared__ __align__(16) float xs[128*16];
    int t = threadIdx.x;
    int z = blockIdx.z;
    const float* W    = (z==0)? wq : (z==1)? wk : wv;
    const float* bias = (z==0)? bq : (z==1)? bk : bv;
    const float* inp  = (z==0)? query : key_feat;
    float* outp       = (z==0)? g_q : (z==1)? g_k : g_v;
    int b  = blockIdx.y;
    int n0 = blockIdx.x * 16;

    for (int idx=t; idx<64*128; idx+=256) Wsm[(idx>>7)*129 + (idx&127)] = W[idx];
    for (int idx=t; idx<128*16; idx+=256) {
        int c = idx>>4, i = idx&15;
        xs[c*16+i] = inp[(b*CIND+c)*NPT + n0 + i];
    }
    __syncthreads();

    int d = t & 63, g = t >> 6;
    float bb = bias[d];
    float acc0=bb, acc1=bb, acc2=bb, acc3=bb;
    for (int c=0; c<128; ++c) {
        float w = Wsm[d*129+c];
        float4 v4 = *(const float4*)&xs[c*16 + g*4];
        acc0 += w*v4.x; acc1 += w*v4.y; acc2 += w*v4.z; acc3 += w*v4.w;
    }
    int pb = (b*NPT + n0 + g*4);
    outp[(pb+0)*DIMD + d] = acc0;
    outp[(pb+1)*DIMD + d] = acc1;
    outp[(pb+2)*DIMD + d] = acc2;
    outp[(pb+3)*DIMD + d] = acc3;
}

// ============================================================================
// Kernel 2: KNN (top-20 smallest d = |p1|^2+|p2|^2-2 p1.p2, stable ties).
// ============================================================================
__global__ __launch_bounds__(128) void knn_kernel(
    const float* __restrict__ pos1, const float* __restrict__ pos2)
{
    __shared__ float4 sp[2048];
    int t = threadIdx.x;
    int b = blockIdx.y;
    int n = blockIdx.x*128 + t;
    const float* p1 = pos1 + b*3*NPT;
    float qx = p1[n], qy = p1[NPT+n], qz = p1[2*NPT+n];
    float s1 = qx*qx + qy*qy + qz*qz;

    float bd[KNNK]; int bi[KNNK];
    #pragma unroll
    for (int i=0;i<KNNK;++i) { bd[i]=1e30f; bi[i]=0; }

    const float* p2 = pos2 + b*3*NS;
    for (int ch=0; ch<2; ++ch) {
        __syncthreads();
        for (int j=t; j<2048; j+=128) {
            int jg = ch*2048 + j;
            float x=p2[jg], y=p2[NS+jg], z=p2[2*NS+jg];
            sp[j] = make_float4(x, y, z, x*x+y*y+z*z);
        }
        __syncthreads();
        for (int j=0; j<2048; ++j) {
            float4 p = sp[j];
            float dd = s1 + p.w - 2.0f*(qx*p.x + qy*p.y + qz*p.z);
            if (dd < bd[KNNK-1]) {
                int jg = ch*2048 + j;
                #pragma unroll
                for (int i=KNNK-1; i>=1; --i) {
                    if (dd < bd[i]) {
                        bool sh = dd < bd[i-1];
                        bd[i] = sh ? bd[i-1] : dd;
                        bi[i] = sh ? bi[i-1] : jg;
                    }
                }
                if (dd < bd[0]) { bd[0]=dd; bi[0]=jg; }
            }
        }
    }
    int* op = &g_idx[(b*NPT + n)*KNNK];
    #pragma unroll
    for (int i=0;i<KNNK;++i) op[i] = bi[i];
}

// ============================================================================
// Kernel 3: gather + pos-MLP; h = q - k_g + pe (fp16 plane); vg fp32.
// pw2 read via __ldg from transposed global (L1-resident 16KB) -> smem 13.4KB
// -> 16 CTAs/SM (occ 100%).
// ============================================================================
__global__ __launch_bounds__(128) void prep_kernel(
    const float* __restrict__ pos1, const float* __restrict__ pos2,
    const float* __restrict__ pw1, const float* __restrict__ pb1,
    const float* __restrict__ pg,  const float* __restrict__ pbt,
    const float* __restrict__ pm,  const float* __restrict__ pvv,
    const float* __restrict__ pb2)
{
    __shared__ __align__(16) float pe1s[2][64*24];
    __shared__ float prel[2][3][KNNK];
    __shared__ float qs[2][64];
    __shared__ int idxs[2][KNNK];
    int t = threadIdx.x;
    int p0 = blockIdx.x*2;

    if (t < 2*KNNK) idxs[t/KNNK][t%KNNK] = g_idx[p0*KNNK + t];
    {
        int pp = t>>6, d = t&63;
        qs[pp][d] = g_q[(p0+pp)*DIMD + d];
    }
    __syncthreads();

    if (t < 2*3*KNNK) {
        int pp = t/(3*KNNK), r = t%(3*KNNK);
        int c = r/KNNK, k = r%KNNK;
        int p = p0+pp, b = p>>12, n = p&4095;
        prel[pp][c][k] = pos1[(b*3+c)*NPT + n] - pos2[(b*3+c)*NS + idxs[pp][k]];
    }
    __syncthreads();

    {
        int cH = t & 63, pp = t >> 6;
        float w0 = pw1[cH*3], w1 = pw1[cH*3+1], w2v = pw1[cH*3+2];
        float inv = pg[cH]*rsqrtf(pvv[cH]+1e-5f);
        float tb  = (pb1[cH]-pm[cH])*inv + pbt[cH];
        #pragma unroll
        for (int k=0;k<KNNK;++k) {
            float s = w0*prel[pp][0][k] + w1*prel[pp][1][k] + w2v*prel[pp][2][k];
            pe1s[pp][cH*24+k] = fmaxf(s*inv + tb, 0.0f);
        }
    }
    __syncthreads();

    {
        int d = t&63, pp = t>>6;
        int p = p0+pp, b = p>>12;
        float acc[KNNK]; float bias = pb2[d];
        #pragma unroll
        for (int k=0;k<KNNK;++k) acc[k]=bias;
        for (int cH=0;cH<64;++cH) {
            float w = __ldg(&g_pw2t[cH*64 + d]);
            #pragma unroll
            for (int k4=0;k4<5;++k4) {
                float4 v4 = *(const float4*)&pe1s[pp][cH*24 + k4*4];
                acc[k4*4+0]+=w*v4.x; acc[k4*4+1]+=w*v4.y;
                acc[k4*4+2]+=w*v4.z; acc[k4*4+3]+=w*v4.w;
            }
        }
        float qv = qs[pp][d];
        #pragma unroll
        for (int k=0;k<KNNK;++k) {
            int j = idxs[pp][k];
            int m = p*KNNK + k;
            float kg = g_k[(b*NS+j)*DIMD + d];
            float vv = g_v[(b*NS+j)*DIMD + d];
            float hv = qv - kg + acc[k];
            g_hh[m*DIMD + d] = __float2half(hv);
            g_vg[m*DIMD + d] = vv + acc[k];
        }
    }
}

// ============================================================================
// Kernel 4 (FUSED, tensor-core): gemm1 + BN/ReLU + gemm2 via 2-product FP16
// mma.m16n8k16 (activations single fp16, weights exact fp16 hi+lo pair).
// CTA = 64 m-rows, block 256 = 8 warps (mw = w&1, cw = w>>1).  [R9 layout]
// ============================================================================
#define HSTW 36
#define ASTW 132
#define OFF_HST 0
#define OFF_AST (64*HSTW)
#define SMEM_ATTN ((64*HSTW + 64*ASTW)*4)

__global__ __launch_bounds__(256, 2) void attn_gemm_kernel()
{
    extern __shared__ __align__(16) unsigned smu[];
    unsigned* hst = smu + OFF_HST;
    unsigned* ast = smu + OFF_AST;
    int t = threadIdx.x;
    int w = t >> 5, lane = t & 31;
    int gr = lane >> 2, tig = lane & 3;
    int mw = w & 1, cw = w >> 1;
    int m0 = blockIdx.x * 64;

    int lr  = lane & 7;
    int lm8 = (lane >> 3) & 1;
    int lk8 = (lane >> 4) & 1;

    {
        const unsigned* hw = (const unsigned*)g_hh;
        for (int idx = t; idx < 64*32; idx += 256) {
            int m = idx >> 5, wk = idx & 31;
            hst[m*HSTW + wk] = hw[(m0+m)*32 + wk];
        }
    }
    __syncthreads();

    uint32_t hb = smem_u32(hst);
    uint32_t ab = smem_u32(ast);

    // ---------------- phase 1: 64m x 256c, K=64 (4 k16 steps) ----------------
    {
        float acc[2][8][4];
        #pragma unroll
        for (int mf=0;mf<2;++mf)
            #pragma unroll
            for (int nf=0;nf<8;++nf)
                #pragma unroll
                for (int q=0;q<4;++q) acc[mf][nf][q] = 0.f;

        uint32_t ad[2];
        #pragma unroll
        for (int mf=0;mf<2;++mf) {
            int row = mw*32 + mf*16 + lm8*8 + lr;
            ad[mf] = hb + (uint32_t)row*(HSTW*4) + (uint32_t)lk8*16;
        }

        #pragma unroll
        for (int s=0; s<4; ++s) {
            unsigned av[2][4];
            #pragma unroll
            for (int mf=0;mf<2;++mf) ldsm_x4(av[mf], ad[mf] + s*32);
            #pragma unroll
            for (int half=0; half<2; ++half) {
                uint4 wf[4];
                #pragma unroll
                for (int j=0;j<4;++j)
                    wf[j] = __ldg((const uint4*)&g_w1f[((s*32 + cw*8 + half*4 + j)*32 + lane)*4]);
                #pragma unroll
                for (int j=0;j<4;++j) {
                    int nf = half*4 + j;
                    unsigned bhi[2] = {wf[j].x, wf[j].y};
                    unsigned blo[2] = {wf[j].z, wf[j].w};
                    #pragma unroll
                    for (int mf=0;mf<2;++mf) {
                        mma_f16(acc[mf][nf], av[mf], bhi);
                        mma_f16(acc[mf][nf], av[mf], blo);
                    }
                }
            }
        }

        // epilogue: BN + ReLU -> fp16 plane
        #pragma unroll
        for (int nf=0;nf<8;++nf) {
            int cb = cw*64 + nf*8 + 2*tig;
            int wd = cw*32 + nf*4 + tig;
            float2 iv = __ldg((const float2*)&g_abn[cb]);
            float2 tb = __ldg((const float2*)&g_abn[256+cb]);
            #pragma unroll
            for (int mf=0;mf<2;++mf) {
                int r0 = mw*32 + mf*16 + gr;
                float v0 = fmaxf(fmaf(acc[mf][nf][0], iv.x, tb.x), 0.f);
                float v1 = fmaxf(fmaf(acc[mf][nf][1], iv.y, tb.y), 0.f);
                float v2 = fmaxf(fmaf(acc[mf][nf][2], iv.x, tb.x), 0.f);
                float v3 = fmaxf(fmaf(acc[mf][nf][3], iv.y, tb.y), 0.f);
                __half2 p0 = __halves2half2(__float2half(v0), __float2half(v1));
                __half2 p1 = __halves2half2(__float2half(v2), __float2half(v3));
                ast[(r0  )*ASTW + wd] = *(unsigned*)&p0;
                ast[(r0+8)*ASTW + wd] = *(unsigned*)&p1;
            }
        }
    }
    __syncthreads();

    // ---------------- phase 2: 64m x 128o', K=256 (16 k16 steps) ----------------
    {
        float acc[2][4][4];
        #pragma unroll
        for (int mf=0;mf<2;++mf)
            #pragma unroll
            for (int nf=0;nf<4;++nf)
                #pragma unroll
                for (int q=0;q<4;++q) acc[mf][nf][q] = 0.f;

        uint32_t ad[2];
        #pragma unroll
        for (int mf=0;mf<2;++mf) {
            int row = mw*32 + mf*16 + lm8*8 + lr;
            ad[mf] = ab + (uint32_t)row*(ASTW*4) + (uint32_t)lk8*16;
        }

        #pragma unroll 4
        for (int s=0; s<16; ++s) {
            unsigned av[2][4];
            #pragma unroll
            for (int mf=0;mf<2;++mf) ldsm_x4(av[mf], ad[mf] + s*32);
            uint4 wf[4];
            #pragma unroll
            for (int j=0;j<4;++j)
                wf[j] = __ldg((const uint4*)&g_w2f[((s*16 + cw*4 + j)*32 + lane)*4]);
            #pragma unroll
            for (int j=0;j<4;++j) {
                unsigned bhi[2] = {wf[j].x, wf[j].y};
                unsigned blo[2] = {wf[j].z, wf[j].w};
                #pragma unroll
                for (int mf=0;mf<2;++mf) {
                    mma_f16(acc[mf][j], av[mf], bhi);
                    mma_f16(acc[mf][j], av[mf], blo);
                }
            }
        }

        // epilogue: store logits (float2 per fragment row)
        #pragma unroll
        for (int nf=0;nf<4;++nf) {
            int ob = cw*32 + nf*8 + 2*tig;
            #pragma unroll
            for (int mf=0;mf<2;++mf) {
                int r0 = m0 + mw*32 + mf*16 + gr;
                *(float2*)&g_logits[(r0  )*128 + ob] = make_float2(acc[mf][nf][0], acc[mf][nf][1]);
                *(float2*)&g_logits[(r0+8)*128 + ob] = make_float2(acc[mf][nf][2], acc[mf][nf][3]);
            }
        }
    }
}

// ============================================================================
// Kernel 5: softmax over k (=20) + weighted aggregation of vg.
// ============================================================================
__global__ __launch_bounds__(256) void softmax_kernel()
{
    int t = threadIdx.x;
    int p = blockIdx.x*2 + (t>>7);
    int chn = t & 127;
    int d = chn & 63;

    const float* lp = &g_logits[(size_t)p*KNNK*128 + chn];
    float lg[KNNK];
    #pragma unroll
    for (int k=0;k<KNNK;++k) lg[k] = lp[k*128];
    float mx = lg[0];
    #pragma unroll
    for (int k=1;k<KNNK;++k) mx = fmaxf(mx, lg[k]);
    float s = 0.f;
    #pragma unroll
    for (int k=0;k<KNNK;++k) { lg[k] = __expf(lg[k]-mx); s += lg[k]; }
    float inv = 1.f/s;

    const float* vp = &g_vg[(size_t)p*KNNK*64 + d];
    float acc = 0.f;
    #pragma unroll
    for (int k=0;k<KNNK;++k) acc += lg[k]*vp[k*64];
    g_agg[p*128 + chn] = acc*inv;
}

// ============================================================================
// Kernel 6: final 1x1 conv (DIM->CIN) + residual (nearest-upsampled query).
// ============================================================================
__global__ __launch_bounds__(256) void final_kernel(
    const float* __restrict__ query, const float* __restrict__ be,
    float* __restrict__ out)
{
    __shared__ float wes[64*128];
    __shared__ __align__(16) float aggt[64*16];
    int t = threadIdx.x;
    int q0 = blockIdx.x*16;
    for (int idx=t; idx<64*128; idx+=256) wes[idx] = g_wet[idx];
    for (int idx=t; idx<16*64; idx+=256) {
        int li = idx>>6, d = idx&63;
        aggt[d*16+li] = g_agg[(q0+li)*64 + d];
    }
    __syncthreads();

    int o2 = t & 127, h = t >> 7;
    float acc[8];
    #pragma unroll
    for (int i=0;i<8;++i) acc[i]=0.f;
    for (int d=0; d<64; ++d) {
        float w = wes[d*128+o2];
        float4 a0 = *(const float4*)&aggt[d*16 + h*8];
        float4 a1 = *(const float4*)&aggt[d*16 + h*8 + 4];
        acc[0]+=w*a0.x; acc[1]+=w*a0.y; acc[2]+=w*a0.z; acc[3]+=w*a0.w;
        acc[4]+=w*a1.x; acc[5]+=w*a1.y; acc[6]+=w*a1.z; acc[7]+=w*a1.w;
    }
    float bb = be[o2];
    #pragma unroll
    for (int i=0;i<8;++i) {
        int qq = q0 + h*8 + i;
        int b = qq >> 13, nr = qq & 8191, n = nr >> 1;
        out[b*(128*8192) + o2*8192 + nr] = acc[i] + bb
            + query[b*(128*4096) + o2*4096 + n];
    }
}

// ============================================================================
extern "C" void kernel_launch(void* const* d_in, const int* in_sizes, int n_in,
                              void* d_out, int out_size)
{
    const float* pos1     = (const float*)d_in[0];
    const float* query    = (const float*)d_in[1];
    const float* pos2     = (const float*)d_in[2];
    const float* key_feat = (const float*)d_in[3];
    const float* wq  = (const float*)d_in[4];
    const float* bq  = (const float*)d_in[5];
    const float* wk  = (const float*)d_in[6];
    const float* bk  = (const float*)d_in[7];
    const float* wv  = (const float*)d_in[8];
    const float* bv  = (const float*)d_in[9];
    const float* pw1 = (const float*)d_in[10];
    const float* pb1 = (const float*)d_in[11];
    const float* pg  = (const float*)d_in[12];
    const float* pbt = (const float*)d_in[13];
    const float* pm  = (const float*)d_in[14];
    const float* pv  = (const float*)d_in[15];
    const float* pw2 = (const float*)d_in[16];
    const float* pb2 = (const float*)d_in[17];
    const float* aw1 = (const float*)d_in[18];
    const float* ab1 = (const float*)d_in[19];
    const float* ag  = (const float*)d_in[20];
    const float* abt2= (const float*)d_in[21];
    const float* am  = (const float*)d_in[22];
    const float* av  = (const float*)d_in[23];
    const float* awt = (const float*)d_in[24];
    /* abt (d_in[25]) is constant along the softmax axis -> dropped */
    const float* we  = (const float*)d_in[26];
    const float* be  = (const float*)d_in[27];
    float* out = (float*)d_out;

    static int smem_set = 0;
    if (!smem_set) {
        cudaFuncSetAttribute(attn_gemm_kernel,
            cudaFuncAttributeMaxDynamicSharedMemorySize, SMEM_ATTN);
        smem_set = 1;
    }

    setup_kernel<<<96, 256>>>(aw1, awt, we, ag, av, ab1, am, abt2, pw2);
    qkv_kernel<<<dim3(256, NB, 3), 256>>>(query, key_feat, wq, bq, wk, bk, wv, bv);
    knn_kernel<<<dim3(32, NB), 128>>>(pos1, pos2);
    prep_kernel<<<PTOT/2, 128>>>(pos1, pos2, pw1, pb1, pg, pbt, pm, pv, pb2);
    attn_gemm_kernel<<<MTOT/64, 256, SMEM_ATTN>>>();
    softmax_kernel<<<PTOT/2, 256>>>();
    final_kernel<<<PTOT*2/16, 256>>>(query, be, out);
}

// round 14
// speedup vs baseline: 1.2319x; 1.0411x over previous
#include <cuda_runtime.h>
#include <cuda_fp16.h>
#include <cstdint>
#include <math.h>

#define NB   4
#define NPT  4096
#define NS   4096
#define CIND 128
#define DIMD 64
#define KNNK 20
#define MTOT (NB*NPT*KNNK)   /* 327680 */
#define PTOT (NB*NPT)        /* 16384  */

// ---------------- static device scratch (no runtime allocation) ----------------
__device__ float g_q[PTOT*DIMD];
__device__ float g_k[PTOT*DIMD];
__device__ float g_v[PTOT*DIMD];
__device__ int   g_idx[PTOT*KNNK];
__device__ __half g_hh[MTOT*DIMD];    // h (fp16, single plane)
__device__ float g_vg[MTOT*DIMD];     // [m][d]
__device__ float g_logits[MTOT*128];  // [m][r*64+o]
__device__ float g_agg[PTOT*2*DIMD];  // [q][d], q = point*2+r
__device__ float g_wet[64*128];       // [d][o2]  transposed we
__device__ float g_pw2t[64*64];       // [cH][d]  transposed pw2 (prep weight)
__device__ float g_abn[512];          // [0:256) inv, [256:512) fused bias
// fragment-ordered fp16 weights (single plane): uint2 = (b0, b1)
__device__ unsigned g_w1f[4*32*32*2];   // [s<4][nfg<32][lane][2]
__device__ unsigned g_w2f[16*16*32*2];  // [s<16][nfg<16][lane][2]

// ---------------- helpers ----------------
__device__ __forceinline__ void mma_f16(float* d, const unsigned* a, const unsigned* b) {
    asm volatile(
        "mma.sync.aligned.m16n8k16.row.col.f32.f16.f16.f32 "
        "{%0,%1,%2,%3}, {%4,%5,%6,%7}, {%8,%9}, {%0,%1,%2,%3};"
        : "+f"(d[0]), "+f"(d[1]), "+f"(d[2]), "+f"(d[3])
        : "r"(a[0]), "r"(a[1]), "r"(a[2]), "r"(a[3]), "r"(b[0]), "r"(b[1]));
}
__device__ __forceinline__ void ldsm_x4(unsigned* r, uint32_t addr) {
    asm volatile("ldmatrix.sync.aligned.m8n8.x4.shared.b16 {%0,%1,%2,%3}, [%4];"
        : "=r"(r[0]), "=r"(r[1]), "=r"(r[2]), "=r"(r[3]) : "r"(addr));
}
__device__ __forceinline__ uint32_t smem_u32(const void* p) {
    uint32_t a;
    asm("{ .reg .u64 t; cvta.to.shared.u64 t, %1; cvt.u32.u64 %0, t; }" : "=r"(a) : "l"(p));
    return a;
}

// ============================================================================
// Setup: fragment-order fp16 GEMM weights; fold BN; transpose we and pw2.
// ============================================================================
__global__ void setup_kernel(const float* __restrict__ aw1, const float* __restrict__ awt,
                             const float* __restrict__ we,  const float* __restrict__ ag,
                             const float* __restrict__ av,  const float* __restrict__ ab1,
                             const float* __restrict__ am,  const float* __restrict__ abt2,
                             const float* __restrict__ pw2)
{
    int i0 = blockIdx.x*256 + threadIdx.x;
    int stride = gridDim.x*256;

    // g_w1f: GEMM1 B-frags. B[k][n] = aw1[n*64+k], k<64, n<256. k16 per s.
    for (int i=i0; i<4*32*32; i+=stride) {
        int lane = i & 31, nfg = (i>>5)&31, s = i>>10;
        int gr = lane>>2, tig = lane&3;
        int n = nfg*8 + gr;
        int k0 = s*16 + 2*tig;
        __half2 p0 = __halves2half2(__float2half(aw1[n*64 + k0]),
                                    __float2half(aw1[n*64 + k0+1]));
        __half2 p1 = __halves2half2(__float2half(aw1[n*64 + k0+8]),
                                    __float2half(aw1[n*64 + k0+9]));
        g_w1f[i*2]   = *(unsigned*)&p0;
        g_w1f[i*2+1] = *(unsigned*)&p1;
    }
    // g_w2f: GEMM2 B-frags. B[k][n=o'] = awt[k*128 + (o'&63)*2 + (o'>>6)].
    for (int i=i0; i<16*16*32; i+=stride) {
        int lane = i & 31, nfg = (i>>5)&15, s = i>>9;
        int gr = lane>>2, tig = lane&3;
        int n = nfg*8 + gr;
        int k0 = s*16 + 2*tig;
        int nn = (n&63)*2 + (n>>6);
        __half2 p0 = __halves2half2(__float2half(awt[(k0  )*128 + nn]),
                                    __float2half(awt[(k0+1)*128 + nn]));
        __half2 p1 = __halves2half2(__float2half(awt[(k0+8)*128 + nn]),
                                    __float2half(awt[(k0+9)*128 + nn]));
        g_w2f[i*2]   = *(unsigned*)&p0;
        g_w2f[i*2+1] = *(unsigned*)&p1;
    }
    for (int i=i0; i<64*128; i+=stride) { int d=i>>7, o2=i&127; g_wet[i] = we[o2*64+d]; }
    for (int i=i0; i<64*64; i+=stride) { int cH=i>>6, d=i&63; g_pw2t[i] = pw2[d*64+cH]; }
    for (int i=i0; i<256; i+=stride) {
        float inv = ag[i]*rsqrtf(av[i]+1e-5f);
        g_abn[i]     = inv;
        g_abn[256+i] = (ab1[i]-am[i])*inv + abt2[i];
    }
}

// ============================================================================
// Kernel 1: q/k/v 1x1 conv.
// ============================================================================
__global__ __launch_bounds__(256) void qkv_kernel(
    const float* __restrict__ query, const float* __restrict__ key_feat,
    const float* __restrict__ wq, const float* __restrict__ bq,
    const float* __restrict__ wk, const float* __restrict__ bk,
    const float* __restrict__ wv, const float* __restrict__ bv)
{
    __shared__ float Wsm[64*129];
    __shared__ __align__(16) float xs[128*16];
    int t = threadIdx.x;
    int z = blockIdx.z;
    const float* W    = (z==0)? wq : (z==1)? wk : wv;
    const float* bias = (z==0)? bq : (z==1)? bk : bv;
    const float* inp  = (z==0)? query : key_feat;
    float* outp       = (z==0)? g_q : (z==1)? g_k : g_v;
    int b  = blockIdx.y;
    int n0 = blockIdx.x * 16;

    for (int idx=t; idx<64*128; idx+=256) Wsm[(idx>>7)*129 + (idx&127)] = W[idx];
    for (int idx=t; idx<128*16; idx+=256) {
        int c = idx>>4, i = idx&15;
        xs[c*16+i] = inp[(b*CIND+c)*NPT + n0 + i];
    }
    __syncthreads();

    int d = t & 63, g = t >> 6;
    float bb = bias[d];
    float acc0=bb, acc1=bb, acc2=bb, acc3=bb;
    for (int c=0; c<128; ++c) {
        float w = Wsm[d*129+c];
        float4 v4 = *(const float4*)&xs[c*16 + g*4];
        acc0 += w*v4.x; acc1 += w*v4.y; acc2 += w*v4.z; acc3 += w*v4.w;
    }
    int pb = (b*NPT + n0 + g*4);
    outp[(pb+0)*DIMD + d] = acc0;
    outp[(pb+1)*DIMD + d] = acc1;
    outp[(pb+2)*DIMD + d] = acc2;
    outp[(pb+3)*DIMD + d] = acc3;
}

// ============================================================================
// Kernel 2: KNN (top-20 smallest d = |p1|^2+|p2|^2-2 p1.p2, stable ties).
// ============================================================================
__global__ __launch_bounds__(128) void knn_kernel(
    const float* __restrict__ pos1, const float* __restrict__ pos2)
{
    __shared__ float4 sp[2048];
    int t = threadIdx.x;
    int b = blockIdx.y;
    int n = blockIdx.x*128 + t;
    const float* p1 = pos1 + b*3*NPT;
    float qx = p1[n], qy = p1[NPT+n], qz = p1[2*NPT+n];
    float s1 = qx*qx + qy*qy + qz*qz;

    float bd[KNNK]; int bi[KNNK];
    #pragma unroll
    for (int i=0;i<KNNK;++i) { bd[i]=1e30f; bi[i]=0; }

    const float* p2 = pos2 + b*3*NS;
    for (int ch=0; ch<2; ++ch) {
        __syncthreads();
        for (int j=t; j<2048; j+=128) {
            int jg = ch*2048 + j;
            float x=p2[jg], y=p2[NS+jg], z=p2[2*NS+jg];
            sp[j] = make_float4(x, y, z, x*x+y*y+z*z);
        }
        __syncthreads();
        for (int j=0; j<2048; ++j) {
            float4 p = sp[j];
            float dd = s1 + p.w - 2.0f*(qx*p.x + qy*p.y + qz*p.z);
            if (dd < bd[KNNK-1]) {
                int jg = ch*2048 + j;
                #pragma unroll
                for (int i=KNNK-1; i>=1; --i) {
                    if (dd < bd[i]) {
                        bool sh = dd < bd[i-1];
                        bd[i] = sh ? bd[i-1] : dd;
                        bi[i] = sh ? bi[i-1] : jg;
                    }
                }
                if (dd < bd[0]) { bd[0]=dd; bi[0]=jg; }
            }
        }
    }
    int* op = &g_idx[(b*NPT + n)*KNNK];
    #pragma unroll
    for (int i=0;i<KNNK;++i) op[i] = bi[i];
}

// ============================================================================
// Kernel 3: gather + pos-MLP; h = q - k_g + pe (fp16 plane); vg fp32.
// ============================================================================
__global__ __launch_bounds__(128) void prep_kernel(
    const float* __restrict__ pos1, const float* __restrict__ pos2,
    const float* __restrict__ pw1, const float* __restrict__ pb1,
    const float* __restrict__ pg,  const float* __restrict__ pbt,
    const float* __restrict__ pm,  const float* __restrict__ pvv,
    const float* __restrict__ pb2)
{
    __shared__ __align__(16) float pe1s[2][64*24];
    __shared__ float prel[2][3][KNNK];
    __shared__ float qs[2][64];
    __shared__ int idxs[2][KNNK];
    int t = threadIdx.x;
    int p0 = blockIdx.x*2;

    if (t < 2*KNNK) idxs[t/KNNK][t%KNNK] = g_idx[p0*KNNK + t];
    {
        int pp = t>>6, d = t&63;
        qs[pp][d] = g_q[(p0+pp)*DIMD + d];
    }
    __syncthreads();

    if (t < 2*3*KNNK) {
        int pp = t/(3*KNNK), r = t%(3*KNNK);
        int c = r/KNNK, k = r%KNNK;
        int p = p0+pp, b = p>>12, n = p&4095;
        prel[pp][c][k] = pos1[(b*3+c)*NPT + n] - pos2[(b*3+c)*NS + idxs[pp][k]];
    }
    __syncthreads();

    {
        int cH = t & 63, pp = t >> 6;
        float w0 = pw1[cH*3], w1 = pw1[cH*3+1], w2v = pw1[cH*3+2];
        float inv = pg[cH]*rsqrtf(pvv[cH]+1e-5f);
        float tb  = (pb1[cH]-pm[cH])*inv + pbt[cH];
        #pragma unroll
        for (int k=0;k<KNNK;++k) {
            float s = w0*prel[pp][0][k] + w1*prel[pp][1][k] + w2v*prel[pp][2][k];
            pe1s[pp][cH*24+k] = fmaxf(s*inv + tb, 0.0f);
        }
    }
    __syncthreads();

    {
        int d = t&63, pp = t>>6;
        int p = p0+pp, b = p>>12;
        float acc[KNNK]; float bias = pb2[d];
        #pragma unroll
        for (int k=0;k<KNNK;++k) acc[k]=bias;
        for (int cH=0;cH<64;++cH) {
            float w = __ldg(&g_pw2t[cH*64 + d]);
            #pragma unroll
            for (int k4=0;k4<5;++k4) {
                float4 v4 = *(const float4*)&pe1s[pp][cH*24 + k4*4];
                acc[k4*4+0]+=w*v4.x; acc[k4*4+1]+=w*v4.y;
                acc[k4*4+2]+=w*v4.z; acc[k4*4+3]+=w*v4.w;
            }
        }
        float qv = qs[pp][d];
        #pragma unroll
        for (int k=0;k<KNNK;++k) {
            int j = idxs[pp][k];
            int m = p*KNNK + k;
            float kg = g_k[(b*NS+j)*DIMD + d];
            float vv = g_v[(b*NS+j)*DIMD + d];
            float hv = qv - kg + acc[k];
            g_hh[m*DIMD + d] = __float2half(hv);
            g_vg[m*DIMD + d] = vv + acc[k];
        }
    }
}

// ============================================================================
// Kernel 4 (FUSED, tensor-core): gemm1 + BN/ReLU + gemm2, single-product FP16
// mma.m16n8k16 (activations and weights both single fp16).
// CTA = 64 m-rows, block 256 = 8 warps (mw = w&1, cw = w>>1).
// ============================================================================
#define HSTW 36
#define ASTW 132
#define OFF_HST 0
#define OFF_AST (64*HSTW)
#define SMEM_ATTN ((64*HSTW + 64*ASTW)*4)

__global__ __launch_bounds__(256, 2) void attn_gemm_kernel()
{
    extern __shared__ __align__(16) unsigned smu[];
    unsigned* hst = smu + OFF_HST;
    unsigned* ast = smu + OFF_AST;
    int t = threadIdx.x;
    int w = t >> 5, lane = t & 31;
    int gr = lane >> 2, tig = lane & 3;
    int mw = w & 1, cw = w >> 1;
    int m0 = blockIdx.x * 64;

    int lr  = lane & 7;
    int lm8 = (lane >> 3) & 1;
    int lk8 = (lane >> 4) & 1;

    {
        const unsigned* hw = (const unsigned*)g_hh;
        for (int idx = t; idx < 64*32; idx += 256) {
            int m = idx >> 5, wk = idx & 31;
            hst[m*HSTW + wk] = hw[(m0+m)*32 + wk];
        }
    }
    __syncthreads();

    uint32_t hb = smem_u32(hst);
    uint32_t ab = smem_u32(ast);

    // ---------------- phase 1: 64m x 256c, K=64 (4 k16 steps) ----------------
    {
        float acc[2][8][4];
        #pragma unroll
        for (int mf=0;mf<2;++mf)
            #pragma unroll
            for (int nf=0;nf<8;++nf)
                #pragma unroll
                for (int q=0;q<4;++q) acc[mf][nf][q] = 0.f;

        uint32_t ad[2];
        #pragma unroll
        for (int mf=0;mf<2;++mf) {
            int row = mw*32 + mf*16 + lm8*8 + lr;
            ad[mf] = hb + (uint32_t)row*(HSTW*4) + (uint32_t)lk8*16;
        }

        #pragma unroll
        for (int s=0; s<4; ++s) {
            unsigned av[2][4];
            #pragma unroll
            for (int mf=0;mf<2;++mf) ldsm_x4(av[mf], ad[mf] + s*32);
            #pragma unroll
            for (int half=0; half<2; ++half) {
                uint2 wf[4];
                #pragma unroll
                for (int j=0;j<4;++j)
                    wf[j] = __ldg((const uint2*)&g_w1f[((s*32 + cw*8 + half*4 + j)*32 + lane)*2]);
                #pragma unroll
                for (int j=0;j<4;++j) {
                    int nf = half*4 + j;
                    unsigned bb[2] = {wf[j].x, wf[j].y};
                    #pragma unroll
                    for (int mf=0;mf<2;++mf)
                        mma_f16(acc[mf][nf], av[mf], bb);
                }
            }
        }

        // epilogue: BN + ReLU -> fp16 plane
        #pragma unroll
        for (int nf=0;nf<8;++nf) {
            int cb = cw*64 + nf*8 + 2*tig;
            int wd = cw*32 + nf*4 + tig;
            float2 iv = __ldg((const float2*)&g_abn[cb]);
            float2 tb = __ldg((const float2*)&g_abn[256+cb]);
            #pragma unroll
            for (int mf=0;mf<2;++mf) {
                int r0 = mw*32 + mf*16 + gr;
                float v0 = fmaxf(fmaf(acc[mf][nf][0], iv.x, tb.x), 0.f);
                float v1 = fmaxf(fmaf(acc[mf][nf][1], iv.y, tb.y), 0.f);
                float v2 = fmaxf(fmaf(acc[mf][nf][2], iv.x, tb.x), 0.f);
                float v3 = fmaxf(fmaf(acc[mf][nf][3], iv.y, tb.y), 0.f);
                __half2 p0 = __halves2half2(__float2half(v0), __float2half(v1));
                __half2 p1 = __halves2half2(__float2half(v2), __float2half(v3));
                ast[(r0  )*ASTW + wd] = *(unsigned*)&p0;
                ast[(r0+8)*ASTW + wd] = *(unsigned*)&p1;
            }
        }
    }
    __syncthreads();

    // ---------------- phase 2: 64m x 128o', K=256 (16 k16 steps) ----------------
    {
        float acc[2][4][4];
        #pragma unroll
        for (int mf=0;mf<2;++mf)
            #pragma unroll
            for (int nf=0;nf<4;++nf)
                #pragma unroll
                for (int q=0;q<4;++q) acc[mf][nf][q] = 0.f;

        uint32_t ad[2];
        #pragma unroll
        for (int mf=0;mf<2;++mf) {
            int row = mw*32 + mf*16 + lm8*8 + lr;
            ad[mf] = ab + (uint32_t)row*(ASTW*4) + (uint32_t)lk8*16;
        }

        #pragma unroll 4
        for (int s=0; s<16; ++s) {
            unsigned av[2][4];
            #pragma unroll
            for (int mf=0;mf<2;++mf) ldsm_x4(av[mf], ad[mf] + s*32);
            uint2 wf[4];
            #pragma unroll
            for (int j=0;j<4;++j)
                wf[j] = __ldg((const uint2*)&g_w2f[((s*16 + cw*4 + j)*32 + lane)*2]);
            #pragma unroll
            for (int j=0;j<4;++j) {
                unsigned bb[2] = {wf[j].x, wf[j].y};
                #pragma unroll
                for (int mf=0;mf<2;++mf)
                    mma_f16(acc[mf][j], av[mf], bb);
            }
        }

        // epilogue: store logits (float2 per fragment row)
        #pragma unroll
        for (int nf=0;nf<4;++nf) {
            int ob = cw*32 + nf*8 + 2*tig;
            #pragma unroll
            for (int mf=0;mf<2;++mf) {
                int r0 = m0 + mw*32 + mf*16 + gr;
                *(float2*)&g_logits[(r0  )*128 + ob] = make_float2(acc[mf][nf][0], acc[mf][nf][1]);
                *(float2*)&g_logits[(r0+8)*128 + ob] = make_float2(acc[mf][nf][2], acc[mf][nf][3]);
            }
        }
    }
}

// ============================================================================
// Kernel 5: softmax over k (=20) + weighted aggregation of vg.
// ============================================================================
__global__ __launch_bounds__(256) void softmax_kernel()
{
    int t = threadIdx.x;
    int p = blockIdx.x*2 + (t>>7);
    int chn = t & 127;
    int d = chn & 63;

    const float* lp = &g_logits[(size_t)p*KNNK*128 + chn];
    float lg[KNNK];
    #pragma unroll
    for (int k=0;k<KNNK;++k) lg[k] = lp[k*128];
    float mx = lg[0];
    #pragma unroll
    for (int k=1;k<KNNK;++k) mx = fmaxf(mx, lg[k]);
    float s = 0.f;
    #pragma unroll
    for (int k=0;k<KNNK;++k) { lg[k] = __expf(lg[k]-mx); s += lg[k]; }
    float inv = 1.f/s;

    const float* vp = &g_vg[(size_t)p*KNNK*64 + d];
    float acc = 0.f;
    #pragma unroll
    for (int k=0;k<KNNK;++k) acc += lg[k]*vp[k*64];
    g_agg[p*128 + chn] = acc*inv;
}

// ============================================================================
// Kernel 6: final 1x1 conv (DIM->CIN) + residual (nearest-upsampled query).
// ============================================================================
__global__ __launch_bounds__(256) void final_kernel(
    const float* __restrict__ query, const float* __restrict__ be,
    float* __restrict__ out)
{
    __shared__ float wes[64*128];
    __shared__ __align__(16) float aggt[64*16];
    int t = threadIdx.x;
    int q0 = blockIdx.x*16;
    for (int idx=t; idx<64*128; idx+=256) wes[idx] = g_wet[idx];
    for (int idx=t; idx<16*64; idx+=256) {
        int li = idx>>6, d = idx&63;
        aggt[d*16+li] = g_agg[(q0+li)*64 + d];
    }
    __syncthreads();

    int o2 = t & 127, h = t >> 7;
    float acc[8];
    #pragma unroll
    for (int i=0;i<8;++i) acc[i]=0.f;
    for (int d=0; d<64; ++d) {
        float w = wes[d*128+o2];
        float4 a0 = *(const float4*)&aggt[d*16 + h*8];
        float4 a1 = *(const float4*)&aggt[d*16 + h*8 + 4];
        acc[0]+=w*a0.x; acc[1]+=w*a0.y; acc[2]+=w*a0.z; acc[3]+=w*a0.w;
        acc[4]+=w*a1.x; acc[5]+=w*a1.y; acc[6]+=w*a1.z; acc[7]+=w*a1.w;
    }
    float bb = be[o2];
    #pragma unroll
    for (int i=0;i<8;++i) {
        int qq = q0 + h*8 + i;
        int b = qq >> 13, nr = qq & 8191, n = nr >> 1;
        out[b*(128*8192) + o2*8192 + nr] = acc[i] + bb
            + query[b*(128*4096) + o2*4096 + n];
    }
}

// ============================================================================
extern "C" void kernel_launch(void* const* d_in, const int* in_sizes, int n_in,
                              void* d_out, int out_size)
{
    const float* pos1     = (const float*)d_in[0];
    const float* query    = (const float*)d_in[1];
    const float* pos2     = (const float*)d_in[2];
    const float* key_feat = (const float*)d_in[3];
    const float* wq  = (const float*)d_in[4];
    const float* bq  = (const float*)d_in[5];
    const float* wk  = (const float*)d_in[6];
    const float* bk  = (const float*)d_in[7];
    const float* wv  = (const float*)d_in[8];
    const float* bv  = (const float*)d_in[9];
    const float* pw1 = (const float*)d_in[10];
    const float* pb1 = (const float*)d_in[11];
    const float* pg  = (const float*)d_in[12];
    const float* pbt = (const float*)d_in[13];
    const float* pm  = (const float*)d_in[14];
    const float* pv  = (const float*)d_in[15];
    const float* pw2 = (const float*)d_in[16];
    const float* pb2 = (const float*)d_in[17];
    const float* aw1 = (const float*)d_in[18];
    const float* ab1 = (const float*)d_in[19];
    const float* ag  = (const float*)d_in[20];
    const float* abt2= (const float*)d_in[21];
    const float* am  = (const float*)d_in[22];
    const float* av  = (const float*)d_in[23];
    const float* awt = (const float*)d_in[24];
    /* abt (d_in[25]) is constant along the softmax axis -> dropped */
    const float* we  = (const float*)d_in[26];
    const float* be  = (const float*)d_in[27];
    float* out = (float*)d_out;

    static int smem_set = 0;
    if (!smem_set) {
        cudaFuncSetAttribute(attn_gemm_kernel,
            cudaFuncAttributeMaxDynamicSharedMemorySize, SMEM_ATTN);
        smem_set = 1;
    }

    setup_kernel<<<96, 256>>>(aw1, awt, we, ag, av, ab1, am, abt2, pw2);
    qkv_kernel<<<dim3(256, NB, 3), 256>>>(query, key_feat, wq, bq, wk, bk, wv, bv);
    knn_kernel<<<dim3(32, NB), 128>>>(pos1, pos2);
    prep_kernel<<<PTOT/2, 128>>>(pos1, pos2, pw1, pb1, pg, pbt, pm, pv, pb2);
    attn_gemm_kernel<<<MTOT/64, 256, SMEM_ATTN>>>();
    softmax_kernel<<<PTOT/2, 256>>>();
    final_kernel<<<PTOT*2/16, 256>>>(query, be, out);
}

// round 16
// speedup vs baseline: 1.2867x; 1.0445x over previous
#include <cuda_runtime.h>
#include <cuda_fp16.h>
#include <cstdint>
#include <math.h>

#define NB   4
#define NPT  4096
#define NS   4096
#define CIND 128
#define DIMD 64
#define KNNK 20
#define MTOT (NB*NPT*KNNK)   /* 327680 */
#define PTOT (NB*NPT)        /* 16384  */

// ---------------- static device scratch (no runtime allocation) ----------------
__device__ float g_q[PTOT*DIMD];
__device__ float g_k[PTOT*DIMD];
__device__ float g_v[PTOT*DIMD];
__device__ int   g_idx[PTOT*KNNK];
__device__ __half g_hh[MTOT*DIMD];     // h (fp16, single plane)
__device__ __half g_vgh[MTOT*DIMD];    // vg (fp16)  [m][d]
__device__ __half g_logith[MTOT*128];  // logits (fp16) [m][r*64+o]
__device__ float g_agg[PTOT*2*DIMD];   // [q][d], q = point*2+r
__device__ float g_wet[64*128];        // [d][o2]  transposed we
__device__ float g_pw2t[64*64];        // [cH][d]  transposed pw2 (prep weight)
__device__ float g_abn[512];           // [0:256) inv, [256:512) fused bias
// fragment-ordered fp16 weights (single plane): uint2 = (b0, b1)
__device__ unsigned g_w1f[4*32*32*2];   // [s<4][nfg<32][lane][2]
__device__ unsigned g_w2f[16*16*32*2];  // [s<16][nfg<16][lane][2]

// ---------------- helpers ----------------
__device__ __forceinline__ void mma_f16(float* d, const unsigned* a, const unsigned* b) {
    asm volatile(
        "mma.sync.aligned.m16n8k16.row.col.f32.f16.f16.f32 "
        "{%0,%1,%2,%3}, {%4,%5,%6,%7}, {%8,%9}, {%0,%1,%2,%3};"
        : "+f"(d[0]), "+f"(d[1]), "+f"(d[2]), "+f"(d[3])
        : "r"(a[0]), "r"(a[1]), "r"(a[2]), "r"(a[3]), "r"(b[0]), "r"(b[1]));
}
__device__ __forceinline__ void ldsm_x4(unsigned* r, uint32_t addr) {
    asm volatile("ldmatrix.sync.aligned.m8n8.x4.shared.b16 {%0,%1,%2,%3}, [%4];"
        : "=r"(r[0]), "=r"(r[1]), "=r"(r[2]), "=r"(r[3]) : "r"(addr));
}
__device__ __forceinline__ uint32_t smem_u32(const void* p) {
    uint32_t a;
    asm("{ .reg .u64 t; cvta.to.shared.u64 t, %1; cvt.u32.u64 %0, t; }" : "=r"(a) : "l"(p));
    return a;
}

// ============================================================================
// Kernel 1: q/k/v 1x1 conv (z = 0..2)  +  weight-prep plane (z = 3).
// grid (256, NB, 4), block 256.
// ============================================================================
__global__ __launch_bounds__(256) void qkv_kernel(
    const float* __restrict__ query, const float* __restrict__ key_feat,
    const float* __restrict__ wq, const float* __restrict__ bq,
    const float* __restrict__ wk, const float* __restrict__ bk,
    const float* __restrict__ wv, const float* __restrict__ bv,
    const float* __restrict__ aw1, const float* __restrict__ awt,
    const float* __restrict__ we,  const float* __restrict__ ag,
    const float* __restrict__ av,  const float* __restrict__ ab1,
    const float* __restrict__ am,  const float* __restrict__ abt2,
    const float* __restrict__ pw2)
{
    __shared__ float Wsm[64*129];
    __shared__ __align__(16) float xs[128*16];
    int t = threadIdx.x;
    int z = blockIdx.z;

    if (z == 3) {   // ---- setup plane: fragment weights, fold BN, transposes ----
        int i0 = (blockIdx.y*256 + blockIdx.x)*256 + t;
        int stride = 256*NB*256;
        for (int i=i0; i<4*32*32; i+=stride) {
            int lane = i & 31, nfg = (i>>5)&31, s = i>>10;
            int gr = lane>>2, tig = lane&3;
            int n = nfg*8 + gr;
            int k0 = s*16 + 2*tig;
            __half2 p0 = __halves2half2(__float2half(aw1[n*64 + k0]),
                                        __float2half(aw1[n*64 + k0+1]));
            __half2 p1 = __halves2half2(__float2half(aw1[n*64 + k0+8]),
                                        __float2half(aw1[n*64 + k0+9]));
            g_w1f[i*2]   = *(unsigned*)&p0;
            g_w1f[i*2+1] = *(unsigned*)&p1;
        }
        for (int i=i0; i<16*16*32; i+=stride) {
            int lane = i & 31, nfg = (i>>5)&15, s = i>>9;
            int gr = lane>>2, tig = lane&3;
            int n = nfg*8 + gr;
            int k0 = s*16 + 2*tig;
            int nn = (n&63)*2 + (n>>6);
            __half2 p0 = __halves2half2(__float2half(awt[(k0  )*128 + nn]),
                                        __float2half(awt[(k0+1)*128 + nn]));
            __half2 p1 = __halves2half2(__float2half(awt[(k0+8)*128 + nn]),
                                        __float2half(awt[(k0+9)*128 + nn]));
            g_w2f[i*2]   = *(unsigned*)&p0;
            g_w2f[i*2+1] = *(unsigned*)&p1;
        }
        for (int i=i0; i<64*128; i+=stride) { int d=i>>7, o2=i&127; g_wet[i] = we[o2*64+d]; }
        for (int i=i0; i<64*64; i+=stride) { int cH=i>>6, d=i&63; g_pw2t[i] = pw2[d*64+cH]; }
        for (int i=i0; i<256; i+=stride) {
            float inv = ag[i]*rsqrtf(av[i]+1e-5f);
            g_abn[i]     = inv;
            g_abn[256+i] = (ab1[i]-am[i])*inv + abt2[i];
        }
        return;
    }

    const float* W    = (z==0)? wq : (z==1)? wk : wv;
    const float* bias = (z==0)? bq : (z==1)? bk : bv;
    const float* inp  = (z==0)? query : key_feat;
    float* outp       = (z==0)? g_q : (z==1)? g_k : g_v;
    int b  = blockIdx.y;
    int n0 = blockIdx.x * 16;

    for (int idx=t; idx<64*128; idx+=256) Wsm[(idx>>7)*129 + (idx&127)] = W[idx];
    for (int idx=t; idx<128*16; idx+=256) {
        int c = idx>>4, i = idx&15;
        xs[c*16+i] = inp[(b*CIND+c)*NPT + n0 + i];
    }
    __syncthreads();

    int d = t & 63, g = t >> 6;
    float bb = bias[d];
    float acc0=bb, acc1=bb, acc2=bb, acc3=bb;
    for (int c=0; c<128; ++c) {
        float w = Wsm[d*129+c];
        float4 v4 = *(const float4*)&xs[c*16 + g*4];
        acc0 += w*v4.x; acc1 += w*v4.y; acc2 += w*v4.z; acc3 += w*v4.w;
    }
    int pb = (b*NPT + n0 + g*4);
    outp[(pb+0)*DIMD + d] = acc0;
    outp[(pb+1)*DIMD + d] = acc1;
    outp[(pb+2)*DIMD + d] = acc2;
    outp[(pb+3)*DIMD + d] = acc3;
}

// ============================================================================
// Kernel 2: KNN (top-20 smallest d = |p1|^2+|p2|^2-2 p1.p2, stable ties).
// ============================================================================
__global__ __launch_bounds__(128) void knn_kernel(
    const float* __restrict__ pos1, const float* __restrict__ pos2)
{
    __shared__ float4 sp[2048];
    int t = threadIdx.x;
    int b = blockIdx.y;
    int n = blockIdx.x*128 + t;
    const float* p1 = pos1 + b*3*NPT;
    float qx = p1[n], qy = p1[NPT+n], qz = p1[2*NPT+n];
    float s1 = qx*qx + qy*qy + qz*qz;

    float bd[KNNK]; int bi[KNNK];
    #pragma unroll
    for (int i=0;i<KNNK;++i) { bd[i]=1e30f; bi[i]=0; }

    const float* p2 = pos2 + b*3*NS;
    for (int ch=0; ch<2; ++ch) {
        __syncthreads();
        for (int j=t; j<2048; j+=128) {
            int jg = ch*2048 + j;
            float x=p2[jg], y=p2[NS+jg], z=p2[2*NS+jg];
            sp[j] = make_float4(x, y, z, x*x+y*y+z*z);
        }
        __syncthreads();
        for (int j=0; j<2048; ++j) {
            float4 p = sp[j];
            float dd = s1 + p.w - 2.0f*(qx*p.x + qy*p.y + qz*p.z);
            if (dd < bd[KNNK-1]) {
                int jg = ch*2048 + j;
                #pragma unroll
                for (int i=KNNK-1; i>=1; --i) {
                    if (dd < bd[i]) {
                        bool sh = dd < bd[i-1];
                        bd[i] = sh ? bd[i-1] : dd;
                        bi[i] = sh ? bi[i-1] : jg;
                    }
                }
                if (dd < bd[0]) { bd[0]=dd; bi[0]=jg; }
            }
        }
    }
    int* op = &g_idx[(b*NPT + n)*KNNK];
    #pragma unroll
    for (int i=0;i<KNNK;++i) op[i] = bi[i];
}

// ============================================================================
// Kernel 3: gather + pos-MLP; h = q - k_g + pe (fp16); vg = v_g + pe (fp16).
// ============================================================================
__global__ __launch_bounds__(128) void prep_kernel(
    const float* __restrict__ pos1, const float* __restrict__ pos2,
    const float* __restrict__ pw1, const float* __restrict__ pb1,
    const float* __restrict__ pg,  const float* __restrict__ pbt,
    const float* __restrict__ pm,  const float* __restrict__ pvv,
    const float* __restrict__ pb2)
{
    __shared__ __align__(16) float pe1s[2][64*24];
    __shared__ float prel[2][3][KNNK];
    __shared__ float qs[2][64];
    __shared__ int idxs[2][KNNK];
    int t = threadIdx.x;
    int p0 = blockIdx.x*2;

    if (t < 2*KNNK) idxs[t/KNNK][t%KNNK] = g_idx[p0*KNNK + t];
    {
        int pp = t>>6, d = t&63;
        qs[pp][d] = g_q[(p0+pp)*DIMD + d];
    }
    __syncthreads();

    if (t < 2*3*KNNK) {
        int pp = t/(3*KNNK), r = t%(3*KNNK);
        int c = r/KNNK, k = r%KNNK;
        int p = p0+pp, b = p>>12, n = p&4095;
        prel[pp][c][k] = pos1[(b*3+c)*NPT + n] - pos2[(b*3+c)*NS + idxs[pp][k]];
    }
    __syncthreads();

    {
        int cH = t & 63, pp = t >> 6;
        float w0 = pw1[cH*3], w1 = pw1[cH*3+1], w2v = pw1[cH*3+2];
        float inv = pg[cH]*rsqrtf(pvv[cH]+1e-5f);
        float tb  = (pb1[cH]-pm[cH])*inv + pbt[cH];
        #pragma unroll
        for (int k=0;k<KNNK;++k) {
            float s = w0*prel[pp][0][k] + w1*prel[pp][1][k] + w2v*prel[pp][2][k];
            pe1s[pp][cH*24+k] = fmaxf(s*inv + tb, 0.0f);
        }
    }
    __syncthreads();

    {
        int d = t&63, pp = t>>6;
        int p = p0+pp, b = p>>12;
        float acc[KNNK]; float bias = pb2[d];
        #pragma unroll
        for (int k=0;k<KNNK;++k) acc[k]=bias;
        for (int cH=0;cH<64;++cH) {
            float w = __ldg(&g_pw2t[cH*64 + d]);
            #pragma unroll
            for (int k4=0;k4<5;++k4) {
                float4 v4 = *(const float4*)&pe1s[pp][cH*24 + k4*4];
                acc[k4*4+0]+=w*v4.x; acc[k4*4+1]+=w*v4.y;
                acc[k4*4+2]+=w*v4.z; acc[k4*4+3]+=w*v4.w;
            }
        }
        float qv = qs[pp][d];
        #pragma unroll
        for (int k=0;k<KNNK;++k) {
            int j = idxs[pp][k];
            int m = p*KNNK + k;
            float kg = g_k[(b*NS+j)*DIMD + d];
            float vv = g_v[(b*NS+j)*DIMD + d];
            float hv = qv - kg + acc[k];
            g_hh [m*DIMD + d] = __float2half(hv);
            g_vgh[m*DIMD + d] = __float2half(vv + acc[k]);
        }
    }
}

// ============================================================================
// Kernel 4 (FUSED, tensor-core): gemm1 + BN/ReLU + gemm2, single-product FP16
// mma.m16n8k16.  CTA = 64 m-rows, block 256 = 8 warps (mw = w&1, cw = w>>1).
// Logits written as fp16 (half2 stores).
// ============================================================================
#define HSTW 36
#define ASTW 132
#define OFF_HST 0
#define OFF_AST (64*HSTW)
#define SMEM_ATTN ((64*HSTW + 64*ASTW)*4)

__global__ __launch_bounds__(256, 2) void attn_gemm_kernel()
{
    extern __shared__ __align__(16) unsigned smu[];
    unsigned* hst = smu + OFF_HST;
    unsigned* ast = smu + OFF_AST;
    int t = threadIdx.x;
    int w = t >> 5, lane = t & 31;
    int gr = lane >> 2, tig = lane & 3;
    int mw = w & 1, cw = w >> 1;
    int m0 = blockIdx.x * 64;

    int lr  = lane & 7;
    int lm8 = (lane >> 3) & 1;
    int lk8 = (lane >> 4) & 1;

    {
        const unsigned* hw = (const unsigned*)g_hh;
        for (int idx = t; idx < 64*32; idx += 256) {
            int m = idx >> 5, wk = idx & 31;
            hst[m*HSTW + wk] = hw[(m0+m)*32 + wk];
        }
    }
    __syncthreads();

    uint32_t hb = smem_u32(hst);
    uint32_t ab = smem_u32(ast);

    // ---------------- phase 1: 64m x 256c, K=64 (4 k16 steps) ----------------
    {
        float acc[2][8][4];
        #pragma unroll
        for (int mf=0;mf<2;++mf)
            #pragma unroll
            for (int nf=0;nf<8;++nf)
                #pragma unroll
                for (int q=0;q<4;++q) acc[mf][nf][q] = 0.f;

        uint32_t ad[2];
        #pragma unroll
        for (int mf=0;mf<2;++mf) {
            int row = mw*32 + mf*16 + lm8*8 + lr;
            ad[mf] = hb + (uint32_t)row*(HSTW*4) + (uint32_t)lk8*16;
        }

        #pragma unroll
        for (int s=0; s<4; ++s) {
            unsigned av[2][4];
            #pragma unroll
            for (int mf=0;mf<2;++mf) ldsm_x4(av[mf], ad[mf] + s*32);
            #pragma unroll
            for (int half=0; half<2; ++half) {
                uint2 wf[4];
                #pragma unroll
                for (int j=0;j<4;++j)
                    wf[j] = __ldg((const uint2*)&g_w1f[((s*32 + cw*8 + half*4 + j)*32 + lane)*2]);
                #pragma unroll
                for (int j=0;j<4;++j) {
                    int nf = half*4 + j;
                    unsigned bb[2] = {wf[j].x, wf[j].y};
                    #pragma unroll
                    for (int mf=0;mf<2;++mf)
                        mma_f16(acc[mf][nf], av[mf], bb);
                }
            }
        }

        // epilogue: BN + ReLU -> fp16 plane
        #pragma unroll
        for (int nf=0;nf<8;++nf) {
            int cb = cw*64 + nf*8 + 2*tig;
            int wd = cw*32 + nf*4 + tig;
            float2 iv = __ldg((const float2*)&g_abn[cb]);
            float2 tb = __ldg((const float2*)&g_abn[256+cb]);
            #pragma unroll
            for (int mf=0;mf<2;++mf) {
                int r0 = mw*32 + mf*16 + gr;
                float v0 = fmaxf(fmaf(acc[mf][nf][0], iv.x, tb.x), 0.f);
                float v1 = fmaxf(fmaf(acc[mf][nf][1], iv.y, tb.y), 0.f);
                float v2 = fmaxf(fmaf(acc[mf][nf][2], iv.x, tb.x), 0.f);
                float v3 = fmaxf(fmaf(acc[mf][nf][3], iv.y, tb.y), 0.f);
                __half2 p0 = __halves2half2(__float2half(v0), __float2half(v1));
                __half2 p1 = __halves2half2(__float2half(v2), __float2half(v3));
                ast[(r0  )*ASTW + wd] = *(unsigned*)&p0;
                ast[(r0+8)*ASTW + wd] = *(unsigned*)&p1;
            }
        }
    }
    __syncthreads();

    // ---------------- phase 2: 64m x 128o', K=256 (16 k16 steps) ----------------
    {
        float acc[2][4][4];
        #pragma unroll
        for (int mf=0;mf<2;++mf)
            #pragma unroll
            for (int nf=0;nf<4;++nf)
                #pragma unroll
                for (int q=0;q<4;++q) acc[mf][nf][q] = 0.f;

        uint32_t ad[2];
        #pragma unroll
        for (int mf=0;mf<2;++mf) {
            int row = mw*32 + mf*16 + lm8*8 + lr;
            ad[mf] = ab + (uint32_t)row*(ASTW*4) + (uint32_t)lk8*16;
        }

        #pragma unroll 4
        for (int s=0; s<16; ++s) {
            unsigned av[2][4];
            #pragma unroll
            for (int mf=0;mf<2;++mf) ldsm_x4(av[mf], ad[mf] + s*32);
            uint2 wf[4];
            #pragma unroll
            for (int j=0;j<4;++j)
                wf[j] = __ldg((const uint2*)&g_w2f[((s*16 + cw*4 + j)*32 + lane)*2]);
            #pragma unroll
            for (int j=0;j<4;++j) {
                unsigned bb[2] = {wf[j].x, wf[j].y};
                #pragma unroll
                for (int mf=0;mf<2;++mf)
                    mma_f16(acc[mf][j], av[mf], bb);
            }
        }

        // epilogue: store logits as fp16 (one half2 word per fragment row-pair)
        unsigned* lw = (unsigned*)g_logith;
        #pragma unroll
        for (int nf=0;nf<4;++nf) {
            int ob = cw*32 + nf*8 + 2*tig;    // even o' index
            int wd = ob >> 1;                 // half2 word index
            #pragma unroll
            for (int mf=0;mf<2;++mf) {
                int r0 = m0 + mw*32 + mf*16 + gr;
                __half2 p0 = __halves2half2(__float2half(acc[mf][nf][0]), __float2half(acc[mf][nf][1]));
                __half2 p1 = __halves2half2(__float2half(acc[mf][nf][2]), __float2half(acc[mf][nf][3]));
                lw[(size_t)(r0  )*64 + wd] = *(unsigned*)&p0;
                lw[(size_t)(r0+8)*64 + wd] = *(unsigned*)&p1;
            }
        }
    }
}

// ============================================================================
// Kernel 5: softmax over k (=20) + weighted aggregation of vg (fp16 inputs).
// ============================================================================
__global__ __launch_bounds__(256) void softmax_kernel()
{
    int t = threadIdx.x;
    int p = blockIdx.x*2 + (t>>7);
    int chn = t & 127;
    int d = chn & 63;

    const __half* lp = &g_logith[(size_t)p*KNNK*128 + chn];
    float lg[KNNK];
    #pragma unroll
    for (int k=0;k<KNNK;++k) lg[k] = __half2float(lp[k*128]);
    float mx = lg[0];
    #pragma unroll
    for (int k=1;k<KNNK;++k) mx = fmaxf(mx, lg[k]);
    float s = 0.f;
    #pragma unroll
    for (int k=0;k<KNNK;++k) { lg[k] = __expf(lg[k]-mx); s += lg[k]; }
    float inv = 1.f/s;

    const __half* vp = &g_vgh[(size_t)p*KNNK*64 + d];
    float acc = 0.f;
    #pragma unroll
    for (int k=0;k<KNNK;++k) acc += lg[k]*__half2float(vp[k*64]);
    g_agg[p*128 + chn] = acc*inv;
}

// ============================================================================
// Kernel 6: final 1x1 conv (DIM->CIN) + residual (nearest-upsampled query).
// ============================================================================
__global__ __launch_bounds__(256) void final_kernel(
    const float* __restrict__ query, const float* __restrict__ be,
    float* __restrict__ out)
{
    __shared__ float wes[64*128];
    __shared__ __align__(16) float aggt[64*16];
    int t = threadIdx.x;
    int q0 = blockIdx.x*16;
    for (int idx=t; idx<64*128; idx+=256) wes[idx] = g_wet[idx];
    for (int idx=t; idx<16*64; idx+=256) {
        int li = idx>>6, d = idx&63;
        aggt[d*16+li] = g_agg[(q0+li)*64 + d];
    }
    __syncthreads();

    int o2 = t & 127, h = t >> 7;
    float acc[8];
    #pragma unroll
    for (int i=0;i<8;++i) acc[i]=0.f;
    for (int d=0; d<64; ++d) {
        float w = wes[d*128+o2];
        float4 a0 = *(const float4*)&aggt[d*16 + h*8];
        float4 a1 = *(const float4*)&aggt[d*16 + h*8 + 4];
        acc[0]+=w*a0.x; acc[1]+=w*a0.y; acc[2]+=w*a0.z; acc[3]+=w*a0.w;
        acc[4]+=w*a1.x; acc[5]+=w*a1.y; acc[6]+=w*a1.z; acc[7]+=w*a1.w;
    }
    float bb = be[o2];
    #pragma unroll
    for (int i=0;i<8;++i) {
        int qq = q0 + h*8 + i;
        int b = qq >> 13, nr = qq & 8191, n = nr >> 1;
        out[b*(128*8192) + o2*8192 + nr] = acc[i] + bb
            + query[b*(128*4096) + o2*4096 + n];
    }
}

// ============================================================================
extern "C" void kernel_launch(void* const* d_in, const int* in_sizes, int n_in,
                              void* d_out, int out_size)
{
    const float* pos1     = (const float*)d_in[0];
    const float* query    = (const float*)d_in[1];
    const float* pos2     = (const float*)d_in[2];
    const float* key_feat = (const float*)d_in[3];
    const float* wq  = (const float*)d_in[4];
    const float* bq  = (const float*)d_in[5];
    const float* wk  = (const float*)d_in[6];
    const float* bk  = (const float*)d_in[7];
    const float* wv  = (const float*)d_in[8];
    const float* bv  = (const float*)d_in[9];
    const float* pw1 = (const float*)d_in[10];
    const float* pb1 = (const float*)d_in[11];
    const float* pg  = (const float*)d_in[12];
    const float* pbt = (const float*)d_in[13];
    const float* pm  = (const float*)d_in[14];
    const float* pv  = (const float*)d_in[15];
    const float* pw2 = (const float*)d_in[16];
    const float* pb2 = (const float*)d_in[17];
    const float* aw1 = (const float*)d_in[18];
    const float* ab1 = (const float*)d_in[19];
    const float* ag  = (const float*)d_in[20];
    const float* abt2= (const float*)d_in[21];
    const float* am  = (const float*)d_in[22];
    const float* av  = (const float*)d_in[23];
    const float* awt = (const float*)d_in[24];
    /* abt (d_in[25]) is constant along the softmax axis -> dropped */
    const float* we  = (const float*)d_in[26];
    const float* be  = (const float*)d_in[27];
    float* out = (float*)d_out;

    static int smem_set = 0;
    if (!smem_set) {
        cudaFuncSetAttribute(attn_gemm_kernel,
            cudaFuncAttributeMaxDynamicSharedMemorySize, SMEM_ATTN);
        smem_set = 1;
    }

    qkv_kernel<<<dim3(256, NB, 4), 256>>>(query, key_feat, wq, bq, wk, bk, wv, bv,
                                          aw1, awt, we, ag, av, ab1, am, abt2, pw2);
    knn_kernel<<<dim3(32, NB), 128>>>(pos1, pos2);
    prep_kernel<<<PTOT/2, 128>>>(pos1, pos2, pw1, pb1, pg, pbt, pm, pv, pb2);
    attn_gemm_kernel<<<MTOT/64, 256, SMEM_ATTN>>>();
    softmax_kernel<<<PTOT/2, 256>>>();
    final_kernel<<<PTOT*2/16, 256>>>(query, be, out);
}